// round 14
// baseline (speedup 1.0000x reference)
#include <cuda_runtime.h>
#include <stdint.h>

#define N_TBINS 1024
#define TK 96
#define TR 48
#define TT_LO 9000
#define TT_N  2001
#define MAXB  32768
#define MAXREJ 64

__device__ float g_scaled[N_TBINS];
__device__ uint2 g_ksub[TK];
__device__ uint2 g_rs0[TR];
__device__ uint2 g_rs1[TR];
__device__ int   g_tstop;
__device__ float g_lamfake = 10000.0f;  // opaque to the compiler
__device__ uint32_t g_one = 1u;         // opaque 1 -> IMAD on fma pipe
__device__ float g_tt[TT_N];
__device__ float g_partial[MAXB * 3];
__device__ int   g_rejcnt;
__device__ int   g_rejsrc[MAXREJ];
__device__ float g_rejlam[MAXREJ];
__device__ float g_rejpar[MAXREJ * 5];   // log_lam, aa, bb, inv_alpha, v_r
__device__ short g_entry[N_TBINS];       // src -> rejection entry (-1 if knuth)

__device__ __forceinline__ uint32_t rotl32(uint32_t x, int r) {
    return __funnelshift_l(x, x, r);
}

// JAX threefry2x32; two-operand adds as IMAD (fma pipe) via opaque one==1.
__device__ __forceinline__ uint2 threefry2x32(uint2 key, uint32_t x0, uint32_t x1,
                                              uint32_t one) {
    uint32_t ks0 = key.x, ks1 = key.y;
    uint32_t ks2 = ks0 ^ ks1 ^ 0x1BD11BDAu;
#define IMADD(a, b) asm("mad.lo.s32 %0, %1, %2, %0;" : "+r"(a) : "r"(b), "r"(one))
    IMADD(x0, ks0); IMADD(x1, ks1);
#define TF_R(r) { IMADD(x0, x1); x1 = rotl32(x1, r); x1 ^= x0; }
    TF_R(13) TF_R(15) TF_R(26) TF_R(6)
    IMADD(x0, ks1); x1 += ks2 + 1u;
    TF_R(17) TF_R(29) TF_R(16) TF_R(24)
    IMADD(x0, ks2); x1 += ks0 + 2u;
    TF_R(13) TF_R(15) TF_R(26) TF_R(6)
    IMADD(x0, ks0); x1 += ks1 + 3u;
    TF_R(17) TF_R(29) TF_R(16) TF_R(24)
    IMADD(x0, ks1); x1 += ks2 + 4u;
    TF_R(13) TF_R(15) TF_R(26) TF_R(6)
    IMADD(x0, ks2); x1 += ks0 + 5u;
#undef TF_R
#undef IMADD
    return make_uint2(x0, x1);
}

__device__ __forceinline__ float u01(uint2 key, uint32_t j, uint32_t one) {
    uint2 r = threefry2x32(key, 0u, j, one);
    uint32_t bits = r.x ^ r.y;
    return __uint_as_float((bits >> 9) | 0x3f800000u) - 1.0f;
}

// XLA Lanczos lgamma (g=7), x >= 1 here.
__device__ __forceinline__ float lgamma_xla(float x) {
    float z = __fsub_rn(x, 1.0f);
    float sum = 0.99999999999980993f;
    const float lanc[8] = {
        676.520368121885098567009190444019f,
        -1259.13921672240287047156078755283f,
        771.3234287776530788486528258894f,
        -176.61502916214059906584551354f,
        12.507343278686904814458936853f,
        -0.13857109526572011689554707f,
        9.984369578019570859563e-6f,
        1.50563273514931155834e-7f};
#pragma unroll
    for (int i = 0; i < 8; i++) {
        float denom = __fadd_rn(__fadd_rn(z, (float)i), 1.0f);
        sum = __fadd_rn(sum, __fdiv_rn(lanc[i], denom));
    }
    float t = __fadd_rn(7.5f, z);
    float log_t = __fadd_rn(2.0149030205422647f, log1pf(__fdiv_rn(z, 7.5f)));
    float v = __fmul_rn(__fsub_rn(__fadd_rn(z, 0.5f), __fdiv_rn(t, log_t)), log_t);
    return __fadd_rn(__fadd_rn(0.9189385332046727f, v), logf(sum));
}

__device__ __forceinline__ bool rej_step(uint2 s0, uint2 s1, uint32_t j,
                                         float lam, float log_lam, float aa,
                                         float bb, float inv_alpha, float v_r,
                                         bool use_table, uint32_t one,
                                         float& kc_out) {
    float u = __fsub_rn(u01(s0, j, one), 0.5f);
    float v = u01(s1, j, one);
    float us = __fsub_rn(0.5f, fabsf(u));
    float kc = floorf(__fadd_rn(
        __fadd_rn(__fmul_rn(__fadd_rn(__fdiv_rn(__fadd_rn(aa, aa), us), bb), u), lam),
        0.43f));
    kc_out = kc;
    bool accept1 = (us >= 0.07f) && (v <= v_r);
    if (accept1) return true;
    bool reject = (kc < 0.0f) || ((us < 0.013f) && (v > us));
    if (reject) return false;
    float s = logf(__fdiv_rn(__fmul_rn(v, inv_alpha),
                             __fadd_rn(__fdiv_rn(aa, __fmul_rn(us, us)), bb)));
    float tt;
    if (use_table && kc >= (float)TT_LO && kc <= (float)(TT_LO + TT_N - 1)) {
        tt = __ldg(&g_tt[(int)kc - TT_LO]);
    } else {
        tt = __fsub_rn(__fadd_rn(-lam, __fmul_rn(kc, log_lam)),
                       lgamma_xla(__fadd_rn(kc, 1.0f)));
    }
    return s <= tt;
}

__device__ __forceinline__ void rej_params(float lam, float& log_lam, float& aa,
                                           float& bb, float& inv_alpha, float& v_r) {
    log_lam = logf(lam);
    bb = __fadd_rn(0.931f, __fmul_rn(2.53f, sqrtf(lam)));
    aa = __fadd_rn(-0.059f, __fmul_rn(0.02483f, bb));
    inv_alpha = __fadd_rn(1.1239f, __fdiv_rn(1.1328f, __fsub_rn(bb, 3.4f)));
    v_r = __fsub_rn(0.9277f, __fdiv_rn(3.6224f, __fsub_rn(bb, 2.0f)));
}

// chains + tt table + entry map init + counters reset.
__global__ void __launch_bounds__(256, 1)
chains_kernel() {
    int tid = threadIdx.x;
    uint32_t one = g_one;
    if (tid == 0) {
        g_tstop = 0;
        g_rejcnt = 0;
        uint2 key0 = make_uint2(0u, 42u);
        uint2 r = key0;
#pragma unroll 1
        for (int t = 0; t < TK; t++) {
            g_ksub[t] = threefry2x32(r, 0u, 1u, one);
            r = threefry2x32(r, 0u, 0u, one);
        }
        uint2 c = key0;
#pragma unroll 1
        for (int t = 0; t < TR; t++) {
            g_rs0[t] = threefry2x32(c, 0u, 1u, one);
            g_rs1[t] = threefry2x32(c, 0u, 2u, one);
            c = threefry2x32(c, 0u, 0u, one);
        }
    }
#pragma unroll
    for (int i = 0; i < 4; i++) g_entry[tid + i * 256] = -1;
    float lamf = g_lamfake;
    float log_lam = logf(lamf);
#pragma unroll 1
    for (int m = tid; m < TT_N; m += 256) {
        float kc = (float)(TT_LO + m);
        g_tt[m] = __fsub_rn(__fadd_rn(-lamf, __fmul_rn(kc, log_lam)),
                            lgamma_xla(__fadd_rn(kc, 1.0f)));
    }
}

// setup: scaled rates + rejection list with precomputed params + entry map.
__global__ void __launch_bounds__(256, 1)
setup_kernel(const float* __restrict__ ill,
             const float* __restrict__ pc,
             const float* __restrict__ sbr) {
    __shared__ float s[256];
    int tid = threadIdx.x;
    float acc = 0.0f;
#pragma unroll
    for (int i = 0; i < 4; i++) acc = __fadd_rn(acc, ill[tid + i * 256]);
    s[tid] = acc;
    __syncthreads();
    for (int st = 128; st > 0; st >>= 1) {
        if (tid < st) s[tid] = __fadd_rn(s[tid], s[tid + st]);
        __syncthreads();
    }
    float area = s[0];
    float scaling = __fdiv_rn(pc[0], area);
    float amb = __fdiv_rn(__fdiv_rn(pc[0], sbr[0]), 1024.0f);
#pragma unroll
    for (int i = 0; i < 4; i++) {
        int n = tid + i * 256;
        float v = fmaxf(__fadd_rn(__fmul_rn(ill[n], scaling), amb), 0.0f);
        g_scaled[n] = v;
        if (!(v < 10.0f)) {
            int e = atomicAdd(&g_rejcnt, 1);
            if (e < MAXREJ) {
                g_rejsrc[e] = n;
                g_rejlam[e] = v;
                g_entry[n] = (short)e;
                float ll, aa, bb, ia, vr;
                rej_params(v, ll, aa, bb, ia, vr);
                g_rejpar[e * 5 + 0] = ll;
                g_rejpar[e * 5 + 1] = aa;
                g_rejpar[e * 5 + 2] = bb;
                g_rejpar[e * 5 + 3] = ia;
                g_rejpar[e * 5 + 4] = vr;
            }
        }
    }
}

// Kernel A: scan -> tstop; dual-step work-stealing Knuth; partial GEMM.
__global__ void __launch_bounds__(256)
main_kernel(const float* __restrict__ W, const int* __restrict__ labels) {
    __shared__ float s_scaled[N_TBINS];
    __shared__ float s_k[N_TBINS];
    __shared__ short s_entry[N_TBINS];
    __shared__ uint2 s_ksub[TK];
    __shared__ uint2 s_rs0[TR];
    __shared__ uint2 s_rs1[TR];
    __shared__ float s_fake[6];
    __shared__ float s_rpar[MAXREJ * 5];
    __shared__ int s_cur[8];
    __shared__ int s_cur2[8];

    int tid = threadIdx.x;
    int b = blockIdx.x;
    int wid = tid >> 5, lane = tid & 31;
    uint32_t one = g_one;

    for (int i = tid; i < N_TBINS; i += 256) {
        s_scaled[i] = g_scaled[i];
        s_entry[i] = g_entry[i];
    }
    if (tid < TK) s_ksub[tid] = g_ksub[tid];
    if (tid < TR) { s_rs0[tid] = g_rs0[tid]; s_rs1[tid] = g_rs1[tid]; }
    if (tid < MAXREJ * 5 / 2) {
        s_rpar[tid] = g_rejpar[tid];
        s_rpar[tid + MAXREJ * 5 / 2] = g_rejpar[tid + MAXREJ * 5 / 2];
    }
    if (tid < 8) { s_cur[tid] = 32; s_cur2[tid] = 32; }
    if (tid == 0) {
        float lamf = g_lamfake;
        float ll, aa, bb, ia, vr;
        rej_params(lamf, ll, aa, bb, ia, vr);
        s_fake[0] = lamf; s_fake[1] = ll; s_fake[2] = aa;
        s_fake[3] = bb;   s_fake[4] = ia; s_fake[5] = vr;
    }
    __syncthreads();

    int lab = labels[b];
    uint32_t jbase = (uint32_t)b * N_TBINS;

    // ---- phase 0: first-accept scan, work-stealing; params via tables ----
    {
        int tmax = 0;
        float lam, log_lam, aa, bb, inv_alpha, v_r;
        bool use_table = true;
        uint32_t j = 0;
        int t = 0;
        bool active = true;
        {
            int n = wid * 128 + lane;
            int src = (n - lab + N_TBINS) & (N_TBINS - 1);
            float l0 = s_scaled[src];
            if (l0 < 10.0f) {
                lam = s_fake[0]; log_lam = s_fake[1]; aa = s_fake[2];
                bb = s_fake[3]; inv_alpha = s_fake[4]; v_r = s_fake[5];
                use_table = true;
            } else {
                int e = s_entry[src];
                lam = l0;
                log_lam = s_rpar[e * 5 + 0]; aa = s_rpar[e * 5 + 1];
                bb = s_rpar[e * 5 + 2]; inv_alpha = s_rpar[e * 5 + 3];
                v_r = s_rpar[e * 5 + 4];
                use_table = false;
            }
            j = jbase + (uint32_t)n; t = 0;
        }
#pragma unroll 1
        while (__ballot_sync(0xFFFFFFFFu, active)) {
            if (active) {
                float kc;
                bool acc = rej_step(s_rs0[t], s_rs1[t], j, lam, log_lam, aa, bb,
                                    inv_alpha, v_r, use_table, one, kc);
                t++;
                if (acc || t >= TR) {
                    if (acc && t > tmax) tmax = t;
                    int r = atomicAdd(&s_cur[wid], 1);
                    if (r >= 128) {
                        active = false;
                    } else {
                        int n = wid * 128 + r;
                        int src = (n - lab + N_TBINS) & (N_TBINS - 1);
                        float l0 = s_scaled[src];
                        if (l0 < 10.0f) {
                            lam = s_fake[0]; log_lam = s_fake[1]; aa = s_fake[2];
                            bb = s_fake[3]; inv_alpha = s_fake[4]; v_r = s_fake[5];
                            use_table = true;
                        } else {
                            int e = s_entry[src];
                            lam = l0;
                            log_lam = s_rpar[e * 5 + 0]; aa = s_rpar[e * 5 + 1];
                            bb = s_rpar[e * 5 + 2]; inv_alpha = s_rpar[e * 5 + 3];
                            v_r = s_rpar[e * 5 + 4];
                            use_table = false;
                        }
                        j = jbase + (uint32_t)n; t = 0;
                    }
                }
            }
        }
#pragma unroll
        for (int off = 16; off > 0; off >>= 1)
            tmax = max(tmax, __shfl_xor_sync(0xFFFFFFFFu, tmax, off));
        if (lane == 0) atomicMax(&g_tstop, tmax);
    }

    // ---- phase 1: DUAL-STEP work-stealing Knuth over lam<10 bins ----
    {
        float lp = 0.f, neg = 0.f;
        int k = 0, rel = -1;
        uint32_t j = 0;
        bool active = false;
        {
            int r = lane;
            while (true) {
                if (r >= 128) { active = false; break; }
                int n = wid * 128 + r;
                int src = (n - lab + N_TBINS) & (N_TBINS - 1);
                float l0 = s_scaled[src];
                if (l0 < 10.0f) {
                    neg = -l0; lp = 0.f; k = 0; j = jbase + (uint32_t)n;
                    rel = r; active = true; break;
                }
                s_k[n] = 0.0f;
                r = atomicAdd(&s_cur2[wid], 1);
            }
        }
#pragma unroll 1
        while (__ballot_sync(0xFFFFFFFFu, active)) {
            if (active) {
                if (lp > neg && k < TK) {
                    // two independent threefrys in flight (2x ILP);
                    // second step committed only if sequence demands it.
                    float ua = u01(s_ksub[k], j, one);
                    int k1 = (k + 1 < TK) ? (k + 1) : k;
                    float ub = u01(s_ksub[k1], j, one);
                    float la = logf(ua);
                    float lb = logf(ub);
                    float lp1 = __fadd_rn(lp, la);
                    if (lp1 > neg && (k + 1) < TK) {
                        lp = __fadd_rn(lp1, lb);
                        k += 2;
                    } else {
                        lp = lp1;
                        k += 1;
                    }
                } else {
                    s_k[wid * 128 + rel] = (float)(k - 1);
                    int r = atomicAdd(&s_cur2[wid], 1);
                    while (true) {
                        if (r >= 128) { active = false; break; }
                        int n = wid * 128 + r;
                        int src = (n - lab + N_TBINS) & (N_TBINS - 1);
                        float l0 = s_scaled[src];
                        if (l0 < 10.0f) {
                            neg = -l0; lp = 0.f; k = 0; j = jbase + (uint32_t)n;
                            rel = r; break;
                        }
                        s_k[n] = 0.0f;
                        r = atomicAdd(&s_cur2[wid], 1);
                    }
                }
            }
        }
    }
    __syncthreads();

    // ---- phase 2: Knuth-only partial GEMM ----
    float a0 = 0.f, a1 = 0.f, a2 = 0.f;
#pragma unroll
    for (int i = 0; i < 4; i++) {
        int n = tid + i * 256;
        float kv = s_k[n];
        a0 = fmaf(kv, __ldg(&W[n]), a0);
        a1 = fmaf(kv, __ldg(&W[N_TBINS + n]), a1);
        a2 = fmaf(kv, __ldg(&W[2 * N_TBINS + n]), a2);
    }
#pragma unroll
    for (int off = 16; off > 0; off >>= 1) {
        a0 += __shfl_xor_sync(0xFFFFFFFFu, a0, off);
        a1 += __shfl_xor_sync(0xFFFFFFFFu, a1, off);
        a2 += __shfl_xor_sync(0xFFFFFFFFu, a2, off);
    }
    __shared__ float wsum[3][8];
    if (lane == 0) { wsum[0][wid] = a0; wsum[1][wid] = a1; wsum[2][wid] = a2; }
    __syncthreads();
    if (tid < 3) {
        float t = 0.f;
#pragma unroll
        for (int w = 0; w < 8; w++) t += wsum[tid][w];
        g_partial[b * 3 + tid] = t;
    }
}

// Kernel B: warp-per-row, precomputed rejection list + params.
__global__ void __launch_bounds__(256)
finish_kernel(const float* __restrict__ W,
              const int* __restrict__ labels,
              float* __restrict__ out,
              int B) {
    __shared__ uint2 s_rs0[TR];
    __shared__ uint2 s_rs1[TR];
    __shared__ int s_src[MAXREJ];
    __shared__ float s_lam[MAXREJ];
    __shared__ float s_rpar[MAXREJ * 5];
    __shared__ int s_cnt;
    __shared__ int s_tstop;

    int tid = threadIdx.x;
    int wid = tid >> 5, lane = tid & 31;
    uint32_t one = g_one;

    if (tid < TR) { s_rs0[tid] = g_rs0[tid]; s_rs1[tid] = g_rs1[tid]; }
    if (tid == 0) { s_cnt = min(g_rejcnt, MAXREJ); s_tstop = g_tstop; }
    if (tid < MAXREJ) { s_src[tid] = g_rejsrc[tid]; s_lam[tid] = g_rejlam[tid]; }
    if (tid < MAXREJ * 5 / 2) {
        s_rpar[tid] = g_rejpar[tid];
        s_rpar[tid + MAXREJ * 5 / 2] = g_rejpar[tid + MAXREJ * 5 / 2];
    }
    __syncthreads();

    int row = blockIdx.x * 8 + wid;
    if (row >= B) return;
    int cnt = s_cnt;
    int lab = labels[row];
    uint32_t jbase = (uint32_t)row * N_TBINS;
    int tstop = s_tstop;

    float a0 = 0.f, a1 = 0.f, a2 = 0.f;
#pragma unroll 1
    for (int e = lane; e < cnt; e += 32) {
        float lam = s_lam[e];
        float log_lam = s_rpar[e * 5 + 0], aa = s_rpar[e * 5 + 1];
        float bb = s_rpar[e * 5 + 2], inv_alpha = s_rpar[e * 5 + 3];
        float v_r = s_rpar[e * 5 + 4];
        int n = (s_src[e] + lab) & (N_TBINS - 1);
        uint32_t jj = jbase + (uint32_t)n;
        float kval = -1.0f;
#pragma unroll 1
        for (int t = tstop - 1; t >= 0; t--) {
            float kc;
            if (rej_step(s_rs0[t], s_rs1[t], jj, lam, log_lam, aa, bb,
                         inv_alpha, v_r, false, one, kc)) {
                kval = kc;
                break;
            }
        }
        a0 = fmaf(kval, __ldg(&W[n]), a0);
        a1 = fmaf(kval, __ldg(&W[N_TBINS + n]), a1);
        a2 = fmaf(kval, __ldg(&W[2 * N_TBINS + n]), a2);
    }

#pragma unroll
    for (int off = 16; off > 0; off >>= 1) {
        a0 += __shfl_xor_sync(0xFFFFFFFFu, a0, off);
        a1 += __shfl_xor_sync(0xFFFFFFFFu, a1, off);
        a2 += __shfl_xor_sync(0xFFFFFFFFu, a2, off);
    }
    if (lane == 0) {
        out[row * 3 + 0] = a0 + g_partial[row * 3 + 0];
        out[row * 3 + 1] = a1 + g_partial[row * 3 + 1];
        out[row * 3 + 2] = a2 + g_partial[row * 3 + 2];
    }
}

extern "C" void kernel_launch(void* const* d_in, const int* in_sizes, int n_in,
                              void* d_out, int out_size) {
    const float* ill    = (const float*)d_in[0];
    const float* W      = (const float*)d_in[1];
    const int*   labels = (const int*)d_in[2];
    const float* pc     = (const float*)d_in[3];
    const float* sbr    = (const float*)d_in[4];
    int B = in_sizes[2];
    if (B > MAXB) B = MAXB;

    chains_kernel<<<1, 256>>>();
    setup_kernel<<<1, 256>>>(ill, pc, sbr);
    main_kernel<<<B, 256>>>(W, labels);
    finish_kernel<<<(B + 7) / 8, 256>>>(W, labels, (float*)d_out, B);
}

// round 15
// speedup vs baseline: 1.1182x; 1.1182x over previous
#include <cuda_runtime.h>
#include <stdint.h>

#define N_TBINS 1024
#define TK 96
#define TR 48
#define TT_LO 9000
#define TT_N  2001
#define MAXB  32768
#define MAXREJ 64

__device__ float g_scaled[N_TBINS];
__device__ uint2 g_ksub[TK];
__device__ uint2 g_rs0[TR];
__device__ uint2 g_rs1[TR];
__device__ int   g_tstop;
__device__ float g_lamfake = 10000.0f;  // opaque to the compiler
__device__ uint32_t g_one = 1u;         // opaque 1 -> IMAD on fma pipe
__device__ float g_tt[TT_N];
__device__ float g_partial[MAXB * 3];
__device__ int   g_rejcnt;
__device__ int   g_rejsrc[MAXREJ];
__device__ float g_rejlam[MAXREJ];
__device__ float g_rejpar[MAXREJ * 5];   // log_lam, aa, bb, inv_alpha, v_r
__device__ short g_entry[N_TBINS];       // src -> rejection entry (-1 if knuth)

__device__ __forceinline__ uint32_t rotl32(uint32_t x, int r) {
    return __funnelshift_l(x, x, r);
}

// JAX threefry2x32; two-operand adds as IMAD (fma pipe) via opaque one==1.
__device__ __forceinline__ uint2 threefry2x32(uint2 key, uint32_t x0, uint32_t x1,
                                              uint32_t one) {
    uint32_t ks0 = key.x, ks1 = key.y;
    uint32_t ks2 = ks0 ^ ks1 ^ 0x1BD11BDAu;
#define IMADD(a, b) asm("mad.lo.s32 %0, %1, %2, %0;" : "+r"(a) : "r"(b), "r"(one))
    IMADD(x0, ks0); IMADD(x1, ks1);
#define TF_R(r) { IMADD(x0, x1); x1 = rotl32(x1, r); x1 ^= x0; }
    TF_R(13) TF_R(15) TF_R(26) TF_R(6)
    IMADD(x0, ks1); x1 += ks2 + 1u;
    TF_R(17) TF_R(29) TF_R(16) TF_R(24)
    IMADD(x0, ks2); x1 += ks0 + 2u;
    TF_R(13) TF_R(15) TF_R(26) TF_R(6)
    IMADD(x0, ks0); x1 += ks1 + 3u;
    TF_R(17) TF_R(29) TF_R(16) TF_R(24)
    IMADD(x0, ks1); x1 += ks2 + 4u;
    TF_R(13) TF_R(15) TF_R(26) TF_R(6)
    IMADD(x0, ks2); x1 += ks0 + 5u;
#undef TF_R
#undef IMADD
    return make_uint2(x0, x1);
}

__device__ __forceinline__ float u01(uint2 key, uint32_t j, uint32_t one) {
    uint2 r = threefry2x32(key, 0u, j, one);
    uint32_t bits = r.x ^ r.y;
    return __uint_as_float((bits >> 9) | 0x3f800000u) - 1.0f;
}

// XLA Lanczos lgamma (g=7), x >= 1 here.
__device__ __forceinline__ float lgamma_xla(float x) {
    float z = __fsub_rn(x, 1.0f);
    float sum = 0.99999999999980993f;
    const float lanc[8] = {
        676.520368121885098567009190444019f,
        -1259.13921672240287047156078755283f,
        771.3234287776530788486528258894f,
        -176.61502916214059906584551354f,
        12.507343278686904814458936853f,
        -0.13857109526572011689554707f,
        9.984369578019570859563e-6f,
        1.50563273514931155834e-7f};
#pragma unroll
    for (int i = 0; i < 8; i++) {
        float denom = __fadd_rn(__fadd_rn(z, (float)i), 1.0f);
        sum = __fadd_rn(sum, __fdiv_rn(lanc[i], denom));
    }
    float t = __fadd_rn(7.5f, z);
    float log_t = __fadd_rn(2.0149030205422647f, log1pf(__fdiv_rn(z, 7.5f)));
    float v = __fmul_rn(__fsub_rn(__fadd_rn(z, 0.5f), __fdiv_rn(t, log_t)), log_t);
    return __fadd_rn(__fadd_rn(0.9189385332046727f, v), logf(sum));
}

__device__ __forceinline__ bool rej_step(uint2 s0, uint2 s1, uint32_t j,
                                         float lam, float log_lam, float aa,
                                         float bb, float inv_alpha, float v_r,
                                         bool use_table, uint32_t one,
                                         float& kc_out) {
    float u = __fsub_rn(u01(s0, j, one), 0.5f);
    float v = u01(s1, j, one);
    float us = __fsub_rn(0.5f, fabsf(u));
    float kc = floorf(__fadd_rn(
        __fadd_rn(__fmul_rn(__fadd_rn(__fdiv_rn(__fadd_rn(aa, aa), us), bb), u), lam),
        0.43f));
    kc_out = kc;
    bool accept1 = (us >= 0.07f) && (v <= v_r);
    if (accept1) return true;
    bool reject = (kc < 0.0f) || ((us < 0.013f) && (v > us));
    if (reject) return false;
    float s = logf(__fdiv_rn(__fmul_rn(v, inv_alpha),
                             __fadd_rn(__fdiv_rn(aa, __fmul_rn(us, us)), bb)));
    float tt;
    if (use_table && kc >= (float)TT_LO && kc <= (float)(TT_LO + TT_N - 1)) {
        tt = __ldg(&g_tt[(int)kc - TT_LO]);
    } else {
        tt = __fsub_rn(__fadd_rn(-lam, __fmul_rn(kc, log_lam)),
                       lgamma_xla(__fadd_rn(kc, 1.0f)));
    }
    return s <= tt;
}

__device__ __forceinline__ void rej_params(float lam, float& log_lam, float& aa,
                                           float& bb, float& inv_alpha, float& v_r) {
    log_lam = logf(lam);
    bb = __fadd_rn(0.931f, __fmul_rn(2.53f, sqrtf(lam)));
    aa = __fadd_rn(-0.059f, __fmul_rn(0.02483f, bb));
    inv_alpha = __fadd_rn(1.1239f, __fdiv_rn(1.1328f, __fsub_rn(bb, 3.4f)));
    v_r = __fsub_rn(0.9277f, __fdiv_rn(3.6224f, __fsub_rn(bb, 2.0f)));
}

// chains + tt table + entry map init + counters reset.
__global__ void __launch_bounds__(256, 1)
chains_kernel() {
    int tid = threadIdx.x;
    uint32_t one = g_one;
    if (tid == 0) {
        g_tstop = 0;
        g_rejcnt = 0;
        uint2 key0 = make_uint2(0u, 42u);
        uint2 r = key0;
#pragma unroll 1
        for (int t = 0; t < TK; t++) {
            g_ksub[t] = threefry2x32(r, 0u, 1u, one);
            r = threefry2x32(r, 0u, 0u, one);
        }
        uint2 c = key0;
#pragma unroll 1
        for (int t = 0; t < TR; t++) {
            g_rs0[t] = threefry2x32(c, 0u, 1u, one);
            g_rs1[t] = threefry2x32(c, 0u, 2u, one);
            c = threefry2x32(c, 0u, 0u, one);
        }
    }
#pragma unroll
    for (int i = 0; i < 4; i++) g_entry[tid + i * 256] = -1;
    float lamf = g_lamfake;
    float log_lam = logf(lamf);
#pragma unroll 1
    for (int m = tid; m < TT_N; m += 256) {
        float kc = (float)(TT_LO + m);
        g_tt[m] = __fsub_rn(__fadd_rn(-lamf, __fmul_rn(kc, log_lam)),
                            lgamma_xla(__fadd_rn(kc, 1.0f)));
    }
}

// setup: scaled rates + rejection list with precomputed params + entry map.
__global__ void __launch_bounds__(256, 1)
setup_kernel(const float* __restrict__ ill,
             const float* __restrict__ pc,
             const float* __restrict__ sbr) {
    __shared__ float s[256];
    int tid = threadIdx.x;
    float acc = 0.0f;
#pragma unroll
    for (int i = 0; i < 4; i++) acc = __fadd_rn(acc, ill[tid + i * 256]);
    s[tid] = acc;
    __syncthreads();
    for (int st = 128; st > 0; st >>= 1) {
        if (tid < st) s[tid] = __fadd_rn(s[tid], s[tid + st]);
        __syncthreads();
    }
    float area = s[0];
    float scaling = __fdiv_rn(pc[0], area);
    float amb = __fdiv_rn(__fdiv_rn(pc[0], sbr[0]), 1024.0f);
#pragma unroll
    for (int i = 0; i < 4; i++) {
        int n = tid + i * 256;
        float v = fmaxf(__fadd_rn(__fmul_rn(ill[n], scaling), amb), 0.0f);
        g_scaled[n] = v;
        if (!(v < 10.0f)) {
            int e = atomicAdd(&g_rejcnt, 1);
            if (e < MAXREJ) {
                g_rejsrc[e] = n;
                g_rejlam[e] = v;
                g_entry[n] = (short)e;
                float ll, aa, bb, ia, vr;
                rej_params(v, ll, aa, bb, ia, vr);
                g_rejpar[e * 5 + 0] = ll;
                g_rejpar[e * 5 + 1] = aa;
                g_rejpar[e * 5 + 2] = bb;
                g_rejpar[e * 5 + 3] = ia;
                g_rejpar[e * 5 + 4] = vr;
            }
        }
    }
}

// Kernel A: scan -> tstop; single-step work-stealing Knuth; partial GEMM.
// 6 blocks/SM forced (reg cap 42) to lift occupancy 61% -> 75%.
__global__ void __launch_bounds__(256, 6)
main_kernel(const float* __restrict__ W, const int* __restrict__ labels) {
    __shared__ float s_scaled[N_TBINS];
    __shared__ float s_k[N_TBINS];
    __shared__ short s_entry[N_TBINS];
    __shared__ uint2 s_ksub[TK];
    __shared__ uint2 s_rs0[TR];
    __shared__ uint2 s_rs1[TR];
    __shared__ float s_fake[6];
    __shared__ float s_rpar[MAXREJ * 5];
    __shared__ int s_cur[8];
    __shared__ int s_cur2[8];

    int tid = threadIdx.x;
    int b = blockIdx.x;
    int wid = tid >> 5, lane = tid & 31;
    uint32_t one = g_one;

    for (int i = tid; i < N_TBINS; i += 256) {
        s_scaled[i] = g_scaled[i];
        s_entry[i] = g_entry[i];
    }
    if (tid < TK) s_ksub[tid] = g_ksub[tid];
    if (tid < TR) { s_rs0[tid] = g_rs0[tid]; s_rs1[tid] = g_rs1[tid]; }
    if (tid < MAXREJ * 5 / 2) {
        s_rpar[tid] = g_rejpar[tid];
        s_rpar[tid + MAXREJ * 5 / 2] = g_rejpar[tid + MAXREJ * 5 / 2];
    }
    if (tid < 8) { s_cur[tid] = 32; s_cur2[tid] = 32; }
    if (tid == 0) {
        float lamf = g_lamfake;
        float ll, aa, bb, ia, vr;
        rej_params(lamf, ll, aa, bb, ia, vr);
        s_fake[0] = lamf; s_fake[1] = ll; s_fake[2] = aa;
        s_fake[3] = bb;   s_fake[4] = ia; s_fake[5] = vr;
    }
    __syncthreads();

    int lab = labels[b];
    uint32_t jbase = (uint32_t)b * N_TBINS;

    // ---- phase 0: first-accept scan, work-stealing; params via tables ----
    {
        int tmax = 0;
        float lam, log_lam, aa, bb, inv_alpha, v_r;
        bool use_table = true;
        uint32_t j = 0;
        int t = 0;
        bool active = true;
        {
            int n = wid * 128 + lane;
            int src = (n - lab + N_TBINS) & (N_TBINS - 1);
            float l0 = s_scaled[src];
            if (l0 < 10.0f) {
                lam = s_fake[0]; log_lam = s_fake[1]; aa = s_fake[2];
                bb = s_fake[3]; inv_alpha = s_fake[4]; v_r = s_fake[5];
                use_table = true;
            } else {
                int e = s_entry[src];
                lam = l0;
                log_lam = s_rpar[e * 5 + 0]; aa = s_rpar[e * 5 + 1];
                bb = s_rpar[e * 5 + 2]; inv_alpha = s_rpar[e * 5 + 3];
                v_r = s_rpar[e * 5 + 4];
                use_table = false;
            }
            j = jbase + (uint32_t)n; t = 0;
        }
#pragma unroll 1
        while (__ballot_sync(0xFFFFFFFFu, active)) {
            if (active) {
                float kc;
                bool acc = rej_step(s_rs0[t], s_rs1[t], j, lam, log_lam, aa, bb,
                                    inv_alpha, v_r, use_table, one, kc);
                t++;
                if (acc || t >= TR) {
                    if (acc && t > tmax) tmax = t;
                    int r = atomicAdd(&s_cur[wid], 1);
                    if (r >= 128) {
                        active = false;
                    } else {
                        int n = wid * 128 + r;
                        int src = (n - lab + N_TBINS) & (N_TBINS - 1);
                        float l0 = s_scaled[src];
                        if (l0 < 10.0f) {
                            lam = s_fake[0]; log_lam = s_fake[1]; aa = s_fake[2];
                            bb = s_fake[3]; inv_alpha = s_fake[4]; v_r = s_fake[5];
                            use_table = true;
                        } else {
                            int e = s_entry[src];
                            lam = l0;
                            log_lam = s_rpar[e * 5 + 0]; aa = s_rpar[e * 5 + 1];
                            bb = s_rpar[e * 5 + 2]; inv_alpha = s_rpar[e * 5 + 3];
                            v_r = s_rpar[e * 5 + 4];
                            use_table = false;
                        }
                        j = jbase + (uint32_t)n; t = 0;
                    }
                }
            }
        }
#pragma unroll
        for (int off = 16; off > 0; off >>= 1)
            tmax = max(tmax, __shfl_xor_sync(0xFFFFFFFFu, tmax, off));
        if (lane == 0) atomicMax(&g_tstop, tmax);
    }

    // ---- phase 1: single-step work-stealing Knuth over lam<10 bins ----
    {
        float lp = 0.f, neg = 0.f;
        int k = 0, rel = -1;
        uint32_t j = 0;
        bool active = false;
        {
            int r = lane;
            while (true) {
                if (r >= 128) { active = false; break; }
                int n = wid * 128 + r;
                int src = (n - lab + N_TBINS) & (N_TBINS - 1);
                float l0 = s_scaled[src];
                if (l0 < 10.0f) {
                    neg = -l0; lp = 0.f; k = 0; j = jbase + (uint32_t)n;
                    rel = r; active = true; break;
                }
                s_k[n] = 0.0f;
                r = atomicAdd(&s_cur2[wid], 1);
            }
        }
#pragma unroll 1
        while (__ballot_sync(0xFFFFFFFFu, active)) {
            if (active) {
                if (lp > neg && k < TK) {
                    lp = __fadd_rn(lp, logf(u01(s_ksub[k], j, one)));
                    k++;
                } else {
                    s_k[wid * 128 + rel] = (float)(k - 1);
                    int r = atomicAdd(&s_cur2[wid], 1);
                    while (true) {
                        if (r >= 128) { active = false; break; }
                        int n = wid * 128 + r;
                        int src = (n - lab + N_TBINS) & (N_TBINS - 1);
                        float l0 = s_scaled[src];
                        if (l0 < 10.0f) {
                            neg = -l0; lp = 0.f; k = 0; j = jbase + (uint32_t)n;
                            rel = r; break;
                        }
                        s_k[n] = 0.0f;
                        r = atomicAdd(&s_cur2[wid], 1);
                    }
                }
            }
        }
    }
    __syncthreads();

    // ---- phase 2: Knuth-only partial GEMM ----
    float a0 = 0.f, a1 = 0.f, a2 = 0.f;
#pragma unroll
    for (int i = 0; i < 4; i++) {
        int n = tid + i * 256;
        float kv = s_k[n];
        a0 = fmaf(kv, __ldg(&W[n]), a0);
        a1 = fmaf(kv, __ldg(&W[N_TBINS + n]), a1);
        a2 = fmaf(kv, __ldg(&W[2 * N_TBINS + n]), a2);
    }
#pragma unroll
    for (int off = 16; off > 0; off >>= 1) {
        a0 += __shfl_xor_sync(0xFFFFFFFFu, a0, off);
        a1 += __shfl_xor_sync(0xFFFFFFFFu, a1, off);
        a2 += __shfl_xor_sync(0xFFFFFFFFu, a2, off);
    }
    __shared__ float wsum[3][8];
    if (lane == 0) { wsum[0][wid] = a0; wsum[1][wid] = a1; wsum[2][wid] = a2; }
    __syncthreads();
    if (tid < 3) {
        float t = 0.f;
#pragma unroll
        for (int w = 0; w < 8; w++) t += wsum[tid][w];
        g_partial[b * 3 + tid] = t;
    }
}

// Kernel B: warp-per-row, precomputed rejection list + params.
__global__ void __launch_bounds__(256, 6)
finish_kernel(const float* __restrict__ W,
              const int* __restrict__ labels,
              float* __restrict__ out,
              int B) {
    __shared__ uint2 s_rs0[TR];
    __shared__ uint2 s_rs1[TR];
    __shared__ int s_src[MAXREJ];
    __shared__ float s_lam[MAXREJ];
    __shared__ float s_rpar[MAXREJ * 5];
    __shared__ int s_cnt;
    __shared__ int s_tstop;

    int tid = threadIdx.x;
    int wid = tid >> 5, lane = tid & 31;
    uint32_t one = g_one;

    if (tid < TR) { s_rs0[tid] = g_rs0[tid]; s_rs1[tid] = g_rs1[tid]; }
    if (tid == 0) { s_cnt = min(g_rejcnt, MAXREJ); s_tstop = g_tstop; }
    if (tid < MAXREJ) { s_src[tid] = g_rejsrc[tid]; s_lam[tid] = g_rejlam[tid]; }
    if (tid < MAXREJ * 5 / 2) {
        s_rpar[tid] = g_rejpar[tid];
        s_rpar[tid + MAXREJ * 5 / 2] = g_rejpar[tid + MAXREJ * 5 / 2];
    }
    __syncthreads();

    int row = blockIdx.x * 8 + wid;
    if (row >= B) return;
    int cnt = s_cnt;
    int lab = labels[row];
    uint32_t jbase = (uint32_t)row * N_TBINS;
    int tstop = s_tstop;

    float a0 = 0.f, a1 = 0.f, a2 = 0.f;
#pragma unroll 1
    for (int e = lane; e < cnt; e += 32) {
        float lam = s_lam[e];
        float log_lam = s_rpar[e * 5 + 0], aa = s_rpar[e * 5 + 1];
        float bb = s_rpar[e * 5 + 2], inv_alpha = s_rpar[e * 5 + 3];
        float v_r = s_rpar[e * 5 + 4];
        int n = (s_src[e] + lab) & (N_TBINS - 1);
        uint32_t jj = jbase + (uint32_t)n;
        float kval = -1.0f;
#pragma unroll 1
        for (int t = tstop - 1; t >= 0; t--) {
            float kc;
            if (rej_step(s_rs0[t], s_rs1[t], jj, lam, log_lam, aa, bb,
                         inv_alpha, v_r, false, one, kc)) {
                kval = kc;
                break;
            }
        }
        a0 = fmaf(kval, __ldg(&W[n]), a0);
        a1 = fmaf(kval, __ldg(&W[N_TBINS + n]), a1);
        a2 = fmaf(kval, __ldg(&W[2 * N_TBINS + n]), a2);
    }

#pragma unroll
    for (int off = 16; off > 0; off >>= 1) {
        a0 += __shfl_xor_sync(0xFFFFFFFFu, a0, off);
        a1 += __shfl_xor_sync(0xFFFFFFFFu, a1, off);
        a2 += __shfl_xor_sync(0xFFFFFFFFu, a2, off);
    }
    if (lane == 0) {
        out[row * 3 + 0] = a0 + g_partial[row * 3 + 0];
        out[row * 3 + 1] = a1 + g_partial[row * 3 + 1];
        out[row * 3 + 2] = a2 + g_partial[row * 3 + 2];
    }
}

extern "C" void kernel_launch(void* const* d_in, const int* in_sizes, int n_in,
                              void* d_out, int out_size) {
    const float* ill    = (const float*)d_in[0];
    const float* W      = (const float*)d_in[1];
    const int*   labels = (const int*)d_in[2];
    const float* pc     = (const float*)d_in[3];
    const float* sbr    = (const float*)d_in[4];
    int B = in_sizes[2];
    if (B > MAXB) B = MAXB;

    chains_kernel<<<1, 256>>>();
    setup_kernel<<<1, 256>>>(ill, pc, sbr);
    main_kernel<<<B, 256>>>(W, labels);
    finish_kernel<<<(B + 7) / 8, 256>>>(W, labels, (float*)d_out, B);
}

// round 16
// speedup vs baseline: 1.2333x; 1.1030x over previous
#include <cuda_runtime.h>
#include <stdint.h>

#define N_TBINS 1024
#define TK 96
#define TR 48
#define TT_LO 9000
#define TT_N  2001
#define MAXB  32768
#define MAXREJ 64

__device__ float g_scaled[N_TBINS];
__device__ uint2 g_ksub[TK];
__device__ uint2 g_rs0[TR];
__device__ uint2 g_rs1[TR];
__device__ int   g_tstop;
__device__ float g_lamfake = 10000.0f;  // opaque to the compiler
__device__ uint32_t g_one = 1u;         // opaque 1 -> IMAD on fma pipe
__device__ float g_tt[TT_N];
__device__ float g_partial[MAXB * 3];
__device__ int   g_rejcnt;
__device__ int   g_rejsrc[MAXREJ];
__device__ float g_rejlam[MAXREJ];
__device__ float g_rejpar[MAXREJ * 5];   // log_lam, aa, bb, inv_alpha, v_r
__device__ short g_entry[N_TBINS];       // src -> rejection entry (-1 if knuth)

__device__ __forceinline__ uint32_t rotl32(uint32_t x, int r) {
    return __funnelshift_l(x, x, r);
}

// JAX threefry2x32; two-operand adds as IMAD (fma pipe) via opaque one==1.
__device__ __forceinline__ uint2 threefry2x32(uint2 key, uint32_t x0, uint32_t x1,
                                              uint32_t one) {
    uint32_t ks0 = key.x, ks1 = key.y;
    uint32_t ks2 = ks0 ^ ks1 ^ 0x1BD11BDAu;
#define IMADD(a, b) asm("mad.lo.s32 %0, %1, %2, %0;" : "+r"(a) : "r"(b), "r"(one))
    IMADD(x0, ks0); IMADD(x1, ks1);
#define TF_R(r) { IMADD(x0, x1); x1 = rotl32(x1, r); x1 ^= x0; }
    TF_R(13) TF_R(15) TF_R(26) TF_R(6)
    IMADD(x0, ks1); x1 += ks2 + 1u;
    TF_R(17) TF_R(29) TF_R(16) TF_R(24)
    IMADD(x0, ks2); x1 += ks0 + 2u;
    TF_R(13) TF_R(15) TF_R(26) TF_R(6)
    IMADD(x0, ks0); x1 += ks1 + 3u;
    TF_R(17) TF_R(29) TF_R(16) TF_R(24)
    IMADD(x0, ks1); x1 += ks2 + 4u;
    TF_R(13) TF_R(15) TF_R(26) TF_R(6)
    IMADD(x0, ks2); x1 += ks0 + 5u;
#undef TF_R
#undef IMADD
    return make_uint2(x0, x1);
}

__device__ __forceinline__ float u01(uint2 key, uint32_t j, uint32_t one) {
    uint2 r = threefry2x32(key, 0u, j, one);
    uint32_t bits = r.x ^ r.y;
    return __uint_as_float((bits >> 9) | 0x3f800000u) - 1.0f;
}

// XLA Lanczos lgamma (g=7), x >= 1 here.
__device__ __forceinline__ float lgamma_xla(float x) {
    float z = __fsub_rn(x, 1.0f);
    float sum = 0.99999999999980993f;
    const float lanc[8] = {
        676.520368121885098567009190444019f,
        -1259.13921672240287047156078755283f,
        771.3234287776530788486528258894f,
        -176.61502916214059906584551354f,
        12.507343278686904814458936853f,
        -0.13857109526572011689554707f,
        9.984369578019570859563e-6f,
        1.50563273514931155834e-7f};
#pragma unroll
    for (int i = 0; i < 8; i++) {
        float denom = __fadd_rn(__fadd_rn(z, (float)i), 1.0f);
        sum = __fadd_rn(sum, __fdiv_rn(lanc[i], denom));
    }
    float t = __fadd_rn(7.5f, z);
    float log_t = __fadd_rn(2.0149030205422647f, log1pf(__fdiv_rn(z, 7.5f)));
    float v = __fmul_rn(__fsub_rn(__fadd_rn(z, 0.5f), __fdiv_rn(t, log_t)), log_t);
    return __fadd_rn(__fadd_rn(0.9189385332046727f, v), logf(sum));
}

__device__ __forceinline__ bool rej_step(uint2 s0, uint2 s1, uint32_t j,
                                         float lam, float log_lam, float aa,
                                         float bb, float inv_alpha, float v_r,
                                         bool use_table, uint32_t one,
                                         float& kc_out) {
    float u = __fsub_rn(u01(s0, j, one), 0.5f);
    float v = u01(s1, j, one);
    float us = __fsub_rn(0.5f, fabsf(u));
    float kc = floorf(__fadd_rn(
        __fadd_rn(__fmul_rn(__fadd_rn(__fdiv_rn(__fadd_rn(aa, aa), us), bb), u), lam),
        0.43f));
    kc_out = kc;
    bool accept1 = (us >= 0.07f) && (v <= v_r);
    if (accept1) return true;
    bool reject = (kc < 0.0f) || ((us < 0.013f) && (v > us));
    if (reject) return false;
    float s = logf(__fdiv_rn(__fmul_rn(v, inv_alpha),
                             __fadd_rn(__fdiv_rn(aa, __fmul_rn(us, us)), bb)));
    float tt;
    if (use_table && kc >= (float)TT_LO && kc <= (float)(TT_LO + TT_N - 1)) {
        tt = __ldg(&g_tt[(int)kc - TT_LO]);
    } else {
        tt = __fsub_rn(__fadd_rn(-lam, __fmul_rn(kc, log_lam)),
                       lgamma_xla(__fadd_rn(kc, 1.0f)));
    }
    return s <= tt;
}

__device__ __forceinline__ void rej_params(float lam, float& log_lam, float& aa,
                                           float& bb, float& inv_alpha, float& v_r) {
    log_lam = logf(lam);
    bb = __fadd_rn(0.931f, __fmul_rn(2.53f, sqrtf(lam)));
    aa = __fadd_rn(-0.059f, __fmul_rn(0.02483f, bb));
    inv_alpha = __fadd_rn(1.1239f, __fdiv_rn(1.1328f, __fsub_rn(bb, 3.4f)));
    v_r = __fsub_rn(0.9277f, __fdiv_rn(3.6224f, __fsub_rn(bb, 2.0f)));
}

// chains + tt table + entry map init + counters reset.
__global__ void __launch_bounds__(256, 1)
chains_kernel() {
    int tid = threadIdx.x;
    uint32_t one = g_one;
    if (tid == 0) {
        g_tstop = 0;
        g_rejcnt = 0;
        uint2 key0 = make_uint2(0u, 42u);
        uint2 r = key0;
#pragma unroll 1
        for (int t = 0; t < TK; t++) {
            g_ksub[t] = threefry2x32(r, 0u, 1u, one);
            r = threefry2x32(r, 0u, 0u, one);
        }
        uint2 c = key0;
#pragma unroll 1
        for (int t = 0; t < TR; t++) {
            g_rs0[t] = threefry2x32(c, 0u, 1u, one);
            g_rs1[t] = threefry2x32(c, 0u, 2u, one);
            c = threefry2x32(c, 0u, 0u, one);
        }
    }
#pragma unroll
    for (int i = 0; i < 4; i++) g_entry[tid + i * 256] = -1;
    float lamf = g_lamfake;
    float log_lam = logf(lamf);
#pragma unroll 1
    for (int m = tid; m < TT_N; m += 256) {
        float kc = (float)(TT_LO + m);
        g_tt[m] = __fsub_rn(__fadd_rn(-lamf, __fmul_rn(kc, log_lam)),
                            lgamma_xla(__fadd_rn(kc, 1.0f)));
    }
}

// setup: scaled rates + rejection list with precomputed params + entry map.
__global__ void __launch_bounds__(256, 1)
setup_kernel(const float* __restrict__ ill,
             const float* __restrict__ pc,
             const float* __restrict__ sbr) {
    __shared__ float s[256];
    int tid = threadIdx.x;
    float acc = 0.0f;
#pragma unroll
    for (int i = 0; i < 4; i++) acc = __fadd_rn(acc, ill[tid + i * 256]);
    s[tid] = acc;
    __syncthreads();
    for (int st = 128; st > 0; st >>= 1) {
        if (tid < st) s[tid] = __fadd_rn(s[tid], s[tid + st]);
        __syncthreads();
    }
    float area = s[0];
    float scaling = __fdiv_rn(pc[0], area);
    float amb = __fdiv_rn(__fdiv_rn(pc[0], sbr[0]), 1024.0f);
#pragma unroll
    for (int i = 0; i < 4; i++) {
        int n = tid + i * 256;
        float v = fmaxf(__fadd_rn(__fmul_rn(ill[n], scaling), amb), 0.0f);
        g_scaled[n] = v;
        if (!(v < 10.0f)) {
            int e = atomicAdd(&g_rejcnt, 1);
            if (e < MAXREJ) {
                g_rejsrc[e] = n;
                g_rejlam[e] = v;
                g_entry[n] = (short)e;
                float ll, aa, bb, ia, vr;
                rej_params(v, ll, aa, bb, ia, vr);
                g_rejpar[e * 5 + 0] = ll;
                g_rejpar[e * 5 + 1] = aa;
                g_rejpar[e * 5 + 2] = bb;
                g_rejpar[e * 5 + 3] = ia;
                g_rejpar[e * 5 + 4] = vr;
            }
        }
    }
}

// Kernel A: scan -> tstop; same-trip-complete work-stealing Knuth; partial GEMM.
__global__ void __launch_bounds__(256, 6)
main_kernel(const float* __restrict__ W, const int* __restrict__ labels) {
    __shared__ float s_scaled[N_TBINS];
    __shared__ float s_k[N_TBINS];
    __shared__ short s_entry[N_TBINS];
    __shared__ uint2 s_ksub[TK];
    __shared__ uint2 s_rs0[TR];
    __shared__ uint2 s_rs1[TR];
    __shared__ float s_fake[6];
    __shared__ float s_rpar[MAXREJ * 5];
    __shared__ int s_cur[8];
    __shared__ int s_cur2[8];

    int tid = threadIdx.x;
    int b = blockIdx.x;
    int wid = tid >> 5, lane = tid & 31;
    uint32_t one = g_one;

    for (int i = tid; i < N_TBINS; i += 256) {
        s_scaled[i] = g_scaled[i];
        s_entry[i] = g_entry[i];
    }
    if (tid < TK) s_ksub[tid] = g_ksub[tid];
    if (tid < TR) { s_rs0[tid] = g_rs0[tid]; s_rs1[tid] = g_rs1[tid]; }
    if (tid < MAXREJ * 5 / 2) {
        s_rpar[tid] = g_rejpar[tid];
        s_rpar[tid + MAXREJ * 5 / 2] = g_rejpar[tid + MAXREJ * 5 / 2];
    }
    if (tid < 8) { s_cur[tid] = 32; s_cur2[tid] = 32; }
    if (tid == 0) {
        float lamf = g_lamfake;
        float ll, aa, bb, ia, vr;
        rej_params(lamf, ll, aa, bb, ia, vr);
        s_fake[0] = lamf; s_fake[1] = ll; s_fake[2] = aa;
        s_fake[3] = bb;   s_fake[4] = ia; s_fake[5] = vr;
    }
    __syncthreads();

    int lab = labels[b];
    uint32_t jbase = (uint32_t)b * N_TBINS;

    // ---- phase 0: first-accept scan, work-stealing; params via tables ----
    {
        int tmax = 0;
        float lam, log_lam, aa, bb, inv_alpha, v_r;
        bool use_table = true;
        uint32_t j = 0;
        int t = 0;
        bool active = true;
        {
            int n = wid * 128 + lane;
            int src = (n - lab + N_TBINS) & (N_TBINS - 1);
            float l0 = s_scaled[src];
            if (l0 < 10.0f) {
                lam = s_fake[0]; log_lam = s_fake[1]; aa = s_fake[2];
                bb = s_fake[3]; inv_alpha = s_fake[4]; v_r = s_fake[5];
                use_table = true;
            } else {
                int e = s_entry[src];
                lam = l0;
                log_lam = s_rpar[e * 5 + 0]; aa = s_rpar[e * 5 + 1];
                bb = s_rpar[e * 5 + 2]; inv_alpha = s_rpar[e * 5 + 3];
                v_r = s_rpar[e * 5 + 4];
                use_table = false;
            }
            j = jbase + (uint32_t)n; t = 0;
        }
#pragma unroll 1
        while (__ballot_sync(0xFFFFFFFFu, active)) {
            if (active) {
                float kc;
                bool acc = rej_step(s_rs0[t], s_rs1[t], j, lam, log_lam, aa, bb,
                                    inv_alpha, v_r, use_table, one, kc);
                t++;
                if (acc || t >= TR) {
                    if (acc && t > tmax) tmax = t;
                    int r = atomicAdd(&s_cur[wid], 1);
                    if (r >= 128) {
                        active = false;
                    } else {
                        int n = wid * 128 + r;
                        int src = (n - lab + N_TBINS) & (N_TBINS - 1);
                        float l0 = s_scaled[src];
                        if (l0 < 10.0f) {
                            lam = s_fake[0]; log_lam = s_fake[1]; aa = s_fake[2];
                            bb = s_fake[3]; inv_alpha = s_fake[4]; v_r = s_fake[5];
                            use_table = true;
                        } else {
                            int e = s_entry[src];
                            lam = l0;
                            log_lam = s_rpar[e * 5 + 0]; aa = s_rpar[e * 5 + 1];
                            bb = s_rpar[e * 5 + 2]; inv_alpha = s_rpar[e * 5 + 3];
                            v_r = s_rpar[e * 5 + 4];
                            use_table = false;
                        }
                        j = jbase + (uint32_t)n; t = 0;
                    }
                }
            }
        }
#pragma unroll
        for (int off = 16; off > 0; off >>= 1)
            tmax = max(tmax, __shfl_xor_sync(0xFFFFFFFFu, tmax, off));
        if (lane == 0) atomicMax(&g_tstop, tmax);
    }

    // ---- phase 1: work-stealing Knuth, draw+complete+refill in ONE trip ----
    // Equivalence: original checks (lp>neg && k<TK) BEFORE each draw; since
    // lp=0 > neg=-lam initially (lam>0 always), checking AFTER the draw and
    // stopping when !(lp>neg) || k>=TK yields the identical draw count.
    {
        float lp = 0.f, neg = 0.f;
        int k = 0, rel = -1;
        uint32_t j = 0;
        bool active = false;
        {
            int r = lane;
            while (true) {
                if (r >= 128) { active = false; break; }
                int n = wid * 128 + r;
                int src = (n - lab + N_TBINS) & (N_TBINS - 1);
                float l0 = s_scaled[src];
                if (l0 < 10.0f) {
                    neg = -l0; lp = 0.f; k = 0; j = jbase + (uint32_t)n;
                    rel = r; active = true; break;
                }
                s_k[n] = 0.0f;
                r = atomicAdd(&s_cur2[wid], 1);
            }
        }
#pragma unroll 1
        while (__ballot_sync(0xFFFFFFFFu, active)) {
            if (active) {
                lp = __fadd_rn(lp, logf(u01(s_ksub[k], j, one)));
                k++;
                if (!(lp > neg) || k >= TK) {
                    s_k[wid * 128 + rel] = (float)(k - 1);
                    int r = atomicAdd(&s_cur2[wid], 1);
                    while (true) {
                        if (r >= 128) { active = false; break; }
                        int n = wid * 128 + r;
                        int src = (n - lab + N_TBINS) & (N_TBINS - 1);
                        float l0 = s_scaled[src];
                        if (l0 < 10.0f) {
                            neg = -l0; lp = 0.f; k = 0; j = jbase + (uint32_t)n;
                            rel = r; break;
                        }
                        s_k[n] = 0.0f;
                        r = atomicAdd(&s_cur2[wid], 1);
                    }
                }
            }
        }
    }
    __syncthreads();

    // ---- phase 2: Knuth-only partial GEMM ----
    float a0 = 0.f, a1 = 0.f, a2 = 0.f;
#pragma unroll
    for (int i = 0; i < 4; i++) {
        int n = tid + i * 256;
        float kv = s_k[n];
        a0 = fmaf(kv, __ldg(&W[n]), a0);
        a1 = fmaf(kv, __ldg(&W[N_TBINS + n]), a1);
        a2 = fmaf(kv, __ldg(&W[2 * N_TBINS + n]), a2);
    }
#pragma unroll
    for (int off = 16; off > 0; off >>= 1) {
        a0 += __shfl_xor_sync(0xFFFFFFFFu, a0, off);
        a1 += __shfl_xor_sync(0xFFFFFFFFu, a1, off);
        a2 += __shfl_xor_sync(0xFFFFFFFFu, a2, off);
    }
    __shared__ float wsum[3][8];
    if (lane == 0) { wsum[0][wid] = a0; wsum[1][wid] = a1; wsum[2][wid] = a2; }
    __syncthreads();
    if (tid < 3) {
        float t = 0.f;
#pragma unroll
        for (int w = 0; w < 8; w++) t += wsum[tid][w];
        g_partial[b * 3 + tid] = t;
    }
}

// Kernel B: warp-per-row, precomputed rejection list + params.
__global__ void __launch_bounds__(256, 6)
finish_kernel(const float* __restrict__ W,
              const int* __restrict__ labels,
              float* __restrict__ out,
              int B) {
    __shared__ uint2 s_rs0[TR];
    __shared__ uint2 s_rs1[TR];
    __shared__ int s_src[MAXREJ];
    __shared__ float s_lam[MAXREJ];
    __shared__ float s_rpar[MAXREJ * 5];
    __shared__ int s_cnt;
    __shared__ int s_tstop;

    int tid = threadIdx.x;
    int wid = tid >> 5, lane = tid & 31;
    uint32_t one = g_one;

    if (tid < TR) { s_rs0[tid] = g_rs0[tid]; s_rs1[tid] = g_rs1[tid]; }
    if (tid == 0) { s_cnt = min(g_rejcnt, MAXREJ); s_tstop = g_tstop; }
    if (tid < MAXREJ) { s_src[tid] = g_rejsrc[tid]; s_lam[tid] = g_rejlam[tid]; }
    if (tid < MAXREJ * 5 / 2) {
        s_rpar[tid] = g_rejpar[tid];
        s_rpar[tid + MAXREJ * 5 / 2] = g_rejpar[tid + MAXREJ * 5 / 2];
    }
    __syncthreads();

    int row = blockIdx.x * 8 + wid;
    if (row >= B) return;
    int cnt = s_cnt;
    int lab = labels[row];
    uint32_t jbase = (uint32_t)row * N_TBINS;
    int tstop = s_tstop;

    float a0 = 0.f, a1 = 0.f, a2 = 0.f;
#pragma unroll 1
    for (int e = lane; e < cnt; e += 32) {
        float lam = s_lam[e];
        float log_lam = s_rpar[e * 5 + 0], aa = s_rpar[e * 5 + 1];
        float bb = s_rpar[e * 5 + 2], inv_alpha = s_rpar[e * 5 + 3];
        float v_r = s_rpar[e * 5 + 4];
        int n = (s_src[e] + lab) & (N_TBINS - 1);
        uint32_t jj = jbase + (uint32_t)n;
        float kval = -1.0f;
#pragma unroll 1
        for (int t = tstop - 1; t >= 0; t--) {
            float kc;
            if (rej_step(s_rs0[t], s_rs1[t], jj, lam, log_lam, aa, bb,
                         inv_alpha, v_r, false, one, kc)) {
                kval = kc;
                break;
            }
        }
        a0 = fmaf(kval, __ldg(&W[n]), a0);
        a1 = fmaf(kval, __ldg(&W[N_TBINS + n]), a1);
        a2 = fmaf(kval, __ldg(&W[2 * N_TBINS + n]), a2);
    }

#pragma unroll
    for (int off = 16; off > 0; off >>= 1) {
        a0 += __shfl_xor_sync(0xFFFFFFFFu, a0, off);
        a1 += __shfl_xor_sync(0xFFFFFFFFu, a1, off);
        a2 += __shfl_xor_sync(0xFFFFFFFFu, a2, off);
    }
    if (lane == 0) {
        out[row * 3 + 0] = a0 + g_partial[row * 3 + 0];
        out[row * 3 + 1] = a1 + g_partial[row * 3 + 1];
        out[row * 3 + 2] = a2 + g_partial[row * 3 + 2];
    }
}

extern "C" void kernel_launch(void* const* d_in, const int* in_sizes, int n_in,
                              void* d_out, int out_size) {
    const float* ill    = (const float*)d_in[0];
    const float* W      = (const float*)d_in[1];
    const int*   labels = (const int*)d_in[2];
    const float* pc     = (const float*)d_in[3];
    const float* sbr    = (const float*)d_in[4];
    int B = in_sizes[2];
    if (B > MAXB) B = MAXB;

    chains_kernel<<<1, 256>>>();
    setup_kernel<<<1, 256>>>(ill, pc, sbr);
    main_kernel<<<B, 256>>>(W, labels);
    finish_kernel<<<(B + 7) / 8, 256>>>(W, labels, (float*)d_out, B);
}